// round 12
// baseline (speedup 1.0000x reference)
#include <cuda_runtime.h>
#include <cstdint>

#define BATCH 4
#define LSEQ 4096
#define DMODEL_ 1024
#define DKH 64
#define MROWS (BATCH*LSEQ)   // 16384
#define NQB (LSEQ/64)        // 64 q-blocks per batch
#define KCHUNK 8             // key tiles per split-K work item
#define MAXCH (NQB/KCHUNK)   // 8 chunks max per q-block
#define NTILES (BATCH*NQB)   // 256 key tiles total

// projected q,v as fp16 (half2 packed in uint32), row-major [row][32 half2]
// q pre-scaled by 0.125*log2(e)
__device__ uint32_t g_q[MROWS*32];
__device__ uint32_t g_v[MROWS*32];

// fp16 B-fragment-ordered weights: [slice 3][kt 64][ntp 4][lane 32] uint4
__device__ uint4 g_wf16[3*8192];

// mma-fragment-ordered K/V tiles (fp16): per tile 512 uint4 (8KB)
// g_kf written DIRECTLY by proj (K epilogue is already fragment-shaped)
__device__ uint4 g_kf[NTILES*512];
__device__ uint4 g_vf[NTILES*512];

// split-K partials: item = (b*64+qb)*8 + ci
__device__ float g_opart[(size_t)BATCH*NQB*MAXCH*4096];
__device__ float g_lpart[BATCH*NQB*MAXCH*64];

// pack two fp32 -> half2 (lo in low half)
__device__ __forceinline__ uint32_t packh2(float lo, float hi) {
    uint32_t d;
    asm("cvt.rn.f16x2.f32 %0, %1, %2;" : "=r"(d) : "f"(hi), "f"(lo));
    return d;
}

__device__ __forceinline__ float ex2f(float x) {
    float r;
    asm("ex2.approx.f32 %0, %1;" : "=f"(r) : "f"(x));
    return r;
}

__device__ __forceinline__ void mma_f16(float c[4],
    uint32_t a0, uint32_t a1, uint32_t a2, uint32_t a3,
    uint32_t b0, uint32_t b1)
{
    asm volatile(
        "mma.sync.aligned.m16n8k16.row.col.f32.f16.f16.f32 "
        "{%0,%1,%2,%3}, {%4,%5,%6,%7}, {%8,%9}, {%0,%1,%2,%3};\n"
        : "+f"(c[0]), "+f"(c[1]), "+f"(c[2]), "+f"(c[3])
        : "r"(a0), "r"(a1), "r"(a2), "r"(a3), "r"(b0), "r"(b1));
}

__device__ __forceinline__ void cp16(uint32_t saddr, const void* g) {
    asm volatile("cp.async.cg.shared.global [%0], [%1], 16;" :: "r"(saddr), "l"(g));
}
#define CP_COMMIT() asm volatile("cp.async.commit_group;")
#define CP_WAIT0()  asm volatile("cp.async.wait_group 0;")
#define CP_WAIT2g() asm volatile("cp.async.wait_group 2;")

// ---------------------------------------------------------------------------
// Setup: fp16 fragment-ordered W. idx -> (slice, kt 0..63, ntp 0..3, lane).
// ---------------------------------------------------------------------------
__global__ void wfrag16_kernel(const float* __restrict__ Wq,
                               const float* __restrict__ Wk,
                               const float* __restrict__ Wv)
{
    int idx = blockIdx.x * 256 + threadIdx.x;   // 24576 total
    int slice = idx >> 13;
    int rem = idx & 8191;
    int kt = rem >> 7;
    int ntp = (rem >> 5) & 3;
    int l = rem & 31;
    int g = l >> 2, t = l & 3;
    const float* W = (slice == 0) ? Wq : (slice == 1) ? Wk : Wv;
    int n0 = 2 * ntp * 8 + g;
    int k0 = 16 * kt + 2 * t;
    uint4 v;
    v.x = packh2(W[k0 * DKH + n0],           W[(k0 + 1) * DKH + n0]);
    v.y = packh2(W[(k0 + 8) * DKH + n0],     W[(k0 + 9) * DKH + n0]);
    v.z = packh2(W[k0 * DKH + n0 + 8],       W[(k0 + 1) * DKH + n0 + 8]);
    v.w = packh2(W[(k0 + 8) * DKH + n0 + 8], W[(k0 + 9) * DKH + n0 + 8]);
    g_wf16[idx] = v;
}

// ---------------------------------------------------------------------------
// Projection v6 (fp16 m16n8k16), BARRIER-FREE mainloop:
// 256 threads (8 warps), 128 rows/CTA; warp w autonomously processes its own
// 16 rows. X staged per-warp via cp.async into 3 private buffers
// (wait_group 2 + __syncwarp only — no __syncthreads in the loop).
// W B-frags read directly from g_wf16 via LDG.128 (L1-resident; cp.async.cg
// bypasses L1 so X streaming doesn't evict W).
// Epilogue: z=0 -> g_q rows (scale folds 0.125*log2e); z=1 -> g_kf FRAGMENT-
// DIRECT (proj C-frags == attn K B-frags); z=2 -> g_v rows (repack V only).
// grid = (128, 1, 3)
// ---------------------------------------------------------------------------
#define P6_XSTRIDE 36
#define P6_STAGE_W (16*P6_XSTRIDE)        // 576 words per stage (2304 B)
#define P6_WARP_W (3*P6_STAGE_W)          // 1728 words per warp
#define P6_SMEM_BYTES (8*P6_WARP_W*4)     // 55296 B

__global__ __launch_bounds__(256, 2) void proj6_kernel(
    const float* __restrict__ Qin, const float* __restrict__ Kin, const float* __restrict__ Vin,
    const float* __restrict__ bq, const float* __restrict__ bk, const float* __restrict__ bv)
{
    extern __shared__ float xs[];

    const int which = blockIdx.z;
    const float* X    = (which == 0) ? Qin : (which == 1) ? Kin : Vin;
    const float* bias = (which == 0) ? bq  : (which == 1) ? bk  : bv;
    const float scale = (which == 0) ? 0.125f * 1.44269504088896340736f : 1.0f;

    const int tid = threadIdx.x;
    const int w = tid >> 5;
    const int l = tid & 31;
    const int g = l >> 2;
    const int t = l & 3;
    const int row_base = blockIdx.x * 128;

    float* xw = xs + w * P6_WARP_W;
    const uint32_t xwb = (uint32_t)__cvta_generic_to_shared(xw);
    // warp's 16 rows start at row_base + 16w
    const float* Xp = X + (size_t)(row_base + 16 * w) * DMODEL_;
    const uint4* wsrc = g_wf16 + which * 8192;

    float acc[8][4];
    #pragma unroll
    for (int nt = 0; nt < 8; nt++)
        #pragma unroll
        for (int j = 0; j < 4; j++) acc[nt][j] = 0.f;

    // per-warp async stage of one k=32 chunk into buffer ch%3
    auto issue = [&](int ch) {
        if (ch < 32) {
            uint32_t xb = xwb + (uint32_t)((ch % 3) * P6_STAGE_W) * 4;
            #pragma unroll
            for (int i = 0; i < 4; i++) {
                int f = l + i * 32;            // 128 float4 per chunk
                int r = f >> 3, c = f & 7;
                cp16(xb + (uint32_t)(r * P6_XSTRIDE + c * 4) * 4,
                     Xp + (size_t)r * DMODEL_ + ch * 32 + c * 4);
            }
        }
        CP_COMMIT();    // empty commits past the end keep group counts uniform
    };

    issue(0); issue(1); issue(2);

    for (int ch = 0; ch < 32; ch++) {
        CP_WAIT2g();     // this thread's chunk ch is complete
        __syncwarp();    // warp-wide visibility of all lanes' staged data

        const float* Xc = xw + (ch % 3) * P6_STAGE_W;

        #pragma unroll
        for (int kk = 0; kk < 2; kk++) {
            int cb = kk * 16 + 2 * t;
            float2 q0 = *(const float2*)&Xc[g * P6_XSTRIDE + cb];
            float2 q1 = *(const float2*)&Xc[(g + 8) * P6_XSTRIDE + cb];
            float2 q2 = *(const float2*)&Xc[g * P6_XSTRIDE + cb + 8];
            float2 q3 = *(const float2*)&Xc[(g + 8) * P6_XSTRIDE + cb + 8];
            uint32_t a0 = packh2(q0.x, q0.y);
            uint32_t a1 = packh2(q1.x, q1.y);
            uint32_t a2 = packh2(q2.x, q2.y);
            uint32_t a3 = packh2(q3.x, q3.y);
            #pragma unroll
            for (int ntp = 0; ntp < 4; ntp++) {
                uint4 f = __ldg(&wsrc[((ch * 2 + kk) * 4 + ntp) * 32 + l]);
                mma_f16(acc[2 * ntp],     a0, a1, a2, a3, f.x, f.y);
                mma_f16(acc[2 * ntp + 1], a0, a1, a2, a3, f.z, f.w);
            }
        }

        // refill buffer ch%3 (its LDS data was consumed into registers above)
        issue(ch + 3);
    }

    const int r0 = row_base + 16 * w + g;

    if (which == 1) {
        // K: write attn B-fragments directly (C-frag layout == Kf layout).
        // tile T = row/64; warp's keys are local nt pair {2(w&3), 2(w&3)+1}.
        const int T = (row_base >> 6) + (w >> 2);
        const int ntp = w & 3;
        #pragma unroll
        for (int kt = 0; kt < 4; kt++) {
            int c0 = (2 * kt) * 8 + 2 * t;       // cols of acc[2kt]
            int c1 = (2 * kt + 1) * 8 + 2 * t;   // cols of acc[2kt+1]
            float b00 = bias[c0], b01 = bias[c0 + 1];
            float b10 = bias[c1], b11 = bias[c1 + 1];
            uint4 v;
            v.x = packh2(acc[2 * kt][0] + b00,     acc[2 * kt][1] + b01);
            v.y = packh2(acc[2 * kt + 1][0] + b10, acc[2 * kt + 1][1] + b11);
            v.z = packh2(acc[2 * kt][2] + b00,     acc[2 * kt][3] + b01);
            v.w = packh2(acc[2 * kt + 1][2] + b10, acc[2 * kt + 1][3] + b11);
            g_kf[T * 512 + (kt * 4 + ntp) * 32 + l] = v;
        }
    } else {
        // Q (scaled) / V: row-major half2 words
        uint32_t* Y = (which == 0) ? g_q : g_v;
        #pragma unroll
        for (int nt = 0; nt < 8; nt++) {
            int c = nt * 8 + 2 * t;
            float b0v = bias[c], b1v = bias[c + 1];
            Y[(size_t)r0 * 32 + nt * 4 + t] =
                packh2((acc[nt][0] + b0v) * scale, (acc[nt][1] + b1v) * scale);
            Y[(size_t)(r0 + 8) * 32 + nt * 4 + t] =
                packh2((acc[nt][2] + b0v) * scale, (acc[nt][3] + b1v) * scale);
        }
    }
}

// ---------------------------------------------------------------------------
// Repack V only into PV B-fragment order (K now fused into proj).
// ---------------------------------------------------------------------------
__global__ void repack_kernel()
{
    int idx = blockIdx.x * 256 + threadIdx.x;   // 131072
    int T = idx >> 9;
    int r = idx & 511;
    int kt = r >> 7;
    int ntp = (r >> 5) & 3;
    int l = r & 31;
    int g = l >> 2, t = l & 3;
    int row0 = T * 64;

    const unsigned short* vh = (const unsigned short*)g_v;

    uint4 vv;
    {
        int kr = row0 + kt * 16;
        int nt = 2 * ntp;
        int col = nt * 8 + g;
        unsigned v0 = vh[(size_t)(kr + 2 * t) * 64 + col];
        unsigned v1 = vh[(size_t)(kr + 2 * t + 1) * 64 + col];
        unsigned v2 = vh[(size_t)(kr + 2 * t + 8) * 64 + col];
        unsigned v3 = vh[(size_t)(kr + 2 * t + 9) * 64 + col];
        vv.x = v0 | (v1 << 16);
        vv.y = v2 | (v3 << 16);
        col += 8;
        v0 = vh[(size_t)(kr + 2 * t) * 64 + col];
        v1 = vh[(size_t)(kr + 2 * t + 1) * 64 + col];
        v2 = vh[(size_t)(kr + 2 * t + 8) * 64 + col];
        v3 = vh[(size_t)(kr + 2 * t + 9) * 64 + col];
        vv.z = v0 | (v1 << 16);
        vv.w = v2 | (v3 << 16);
    }
    g_vf[idx] = vv;
}

// ---------------------------------------------------------------------------
// Attention stage 1 (fp16 m16n8k16): split-K partials. (unchanged from R11)
// grid = (8 ci, 64 qb, 4 b)
// ---------------------------------------------------------------------------
#define ATT_SMEM_BYTES 32768

__global__ __launch_bounds__(256, 2) void attn_part_kernel()
{
    extern __shared__ uint4 sm4[];
    const uint32_t smb = (uint32_t)__cvta_generic_to_shared(sm4);

    const int ci = blockIdx.x;
    const int qb = blockIdx.y;
    const int b  = blockIdx.z;
    const int kstart = ci * KCHUNK;
    if (kstart > qb) return;
    const int kend = min(kstart + KCHUNK, qb + 1);

    const int tid = threadIdx.x;
    const int w = tid >> 5;
    const int l = tid & 31;
    const int g = l >> 2;
    const int t = l & 3;
    const int wr = w & 3;
    const int wg = w >> 2;

    uint32_t qa[4][4];
    {
        const uint32_t* qu = g_q + ((size_t)b * LSEQ + (size_t)qb * 64 + 16 * wr + g) * 32;
        const uint32_t* qu8 = qu + 8 * 32;
        #pragma unroll
        for (int kt = 0; kt < 4; kt++) {
            qa[kt][0] = qu[kt * 8 + t];
            qa[kt][1] = qu8[kt * 8 + t];
            qa[kt][2] = qu[kt * 8 + t + 4];
            qa[kt][3] = qu8[kt * 8 + t + 4];
        }
    }

    float o[8][4];
    #pragma unroll
    for (int nt = 0; nt < 8; nt++)
        #pragma unroll
        for (int j = 0; j < 4; j++) o[nt][j] = 0.f;
    float lfrag[4] = {0.f, 0.f, 0.f, 0.f};
    const uint32_t ONES = 0x3C003C00u;

    auto stage = [&](int kb, int p) {
        const uint4* kp = g_kf + (size_t)(b * NQB + kb) * 512;
        const uint4* vp = g_vf + (size_t)(b * NQB + kb) * 512;
        uint32_t kd = smb + (uint32_t)p * 8192;
        uint32_t vd = smb + 16384u + (uint32_t)p * 8192;
        #pragma unroll
        for (int i = 0; i < 2; i++) {
            int u = tid + i * 256;
            cp16(kd + (uint32_t)u * 16, kp + u);
            cp16(vd + (uint32_t)u * 16, vp + u);
        }
        CP_COMMIT();
    };

    stage(kstart, 0);

    for (int kb = kstart; kb < kend; kb++) {
        const int p = (kb - kstart) & 1;
        CP_WAIT0();
        __syncthreads();
        const uint4* Kc = sm4 + p * 512;
        const uint4* Vc = sm4 + 1024 + p * 512;

        if (kb + 1 < kend) stage(kb + 1, 1 - p);

        float s[4][4];
        #pragma unroll
        for (int ntl = 0; ntl < 4; ntl++)
            #pragma unroll
            for (int j = 0; j < 4; j++) s[ntl][j] = 0.f;

        #pragma unroll
        for (int kt = 0; kt < 4; kt++) {
            #pragma unroll
            for (int pp = 0; pp < 2; pp++) {
                uint4 f = Kc[(kt * 4 + wg * 2 + pp) * 32 + l];
                mma_f16(s[2 * pp],     qa[kt][0], qa[kt][1], qa[kt][2], qa[kt][3], f.x, f.y);
                mma_f16(s[2 * pp + 1], qa[kt][0], qa[kt][1], qa[kt][2], qa[kt][3], f.z, f.w);
            }
        }

        if (kb == qb) {
            int r0 = 16 * wr + g;
            #pragma unroll
            for (int ntl = 0; ntl < 4; ntl++) {
                int c = (wg * 4 + ntl) * 8 + 2 * t;
                if (c     > r0)     s[ntl][0] = -1e30f;
                if (c + 1 > r0)     s[ntl][1] = -1e30f;
                if (c     > r0 + 8) s[ntl][2] = -1e30f;
                if (c + 1 > r0 + 8) s[ntl][3] = -1e30f;
            }
        }

        #pragma unroll
        for (int ntl = 0; ntl < 4; ntl++) {
            s[ntl][0] = ex2f(s[ntl][0]);
            s[ntl][1] = ex2f(s[ntl][1]);
            s[ntl][2] = ex2f(s[ntl][2]);
            s[ntl][3] = ex2f(s[ntl][3]);
        }

        #pragma unroll
        for (int kk = 0; kk < 2; kk++) {
            uint32_t a0 = packh2(s[2 * kk][0],     s[2 * kk][1]);
            uint32_t a1 = packh2(s[2 * kk][2],     s[2 * kk][3]);
            uint32_t a2 = packh2(s[2 * kk + 1][0], s[2 * kk + 1][1]);
            uint32_t a3 = packh2(s[2 * kk + 1][2], s[2 * kk + 1][3]);
            mma_f16(lfrag, a0, a1, a2, a3, ONES, ONES);
            int kc = wg * 2 + kk;
            #pragma unroll
            for (int ntp = 0; ntp < 4; ntp++) {
                uint4 f = Vc[(kc * 4 + ntp) * 32 + l];
                mma_f16(o[2 * ntp],     a0, a1, a2, a3, f.x, f.y);
                mma_f16(o[2 * ntp + 1], a0, a1, a2, a3, f.z, f.w);
            }
        }
    }

    const float lsum0 = lfrag[0];
    const float lsum1 = lfrag[2];

    float* smemO = (float*)sm4;
    float* lvec  = (float*)sm4 + 64 * 68;

    __syncthreads();
    if (wg == 0) {
        #pragma unroll
        for (int nt = 0; nt < 8; nt++) {
            int c = nt * 8 + 2 * t;
            smemO[(16 * wr + g) * 68 + c]         = o[nt][0];
            smemO[(16 * wr + g) * 68 + c + 1]     = o[nt][1];
            smemO[(16 * wr + g + 8) * 68 + c]     = o[nt][2];
            smemO[(16 * wr + g + 8) * 68 + c + 1] = o[nt][3];
        }
        if (t == 0) { lvec[16 * wr + g] = lsum0; lvec[16 * wr + g + 8] = lsum1; }
    }
    __syncthreads();
    if (wg == 1) {
        #pragma unroll
        for (int nt = 0; nt < 8; nt++) {
            int c = nt * 8 + 2 * t;
            smemO[(16 * wr + g) * 68 + c]         += o[nt][0];
            smemO[(16 * wr + g) * 68 + c + 1]     += o[nt][1];
            smemO[(16 * wr + g + 8) * 68 + c]     += o[nt][2];
            smemO[(16 * wr + g + 8) * 68 + c + 1] += o[nt][3];
        }
        if (t == 0) { lvec[16 * wr + g] += lsum0; lvec[16 * wr + g + 8] += lsum1; }
    }
    __syncthreads();

    const int item = (b * NQB + qb) * MAXCH + ci;
    {
        int row = tid >> 2;
        int c0 = (tid & 3) * 16;
        float* dst = g_opart + (size_t)item * 4096;
        #pragma unroll
        for (int j = 0; j < 4; j++)
            *(float4*)&dst[row * 64 + c0 + j * 4] = *(float4*)&smemO[row * 68 + c0 + j * 4];
        if ((tid & 3) == 0) g_lpart[item * 64 + row] = lvec[row];
    }
}

// ---------------------------------------------------------------------------
// Attention stage 2: elementwise reduce. (unchanged)
// ---------------------------------------------------------------------------
__global__ __launch_bounds__(256) void attn_reduce_kernel(float* __restrict__ out)
{
    int id = blockIdx.x * 256 + threadIdx.x;   // 262144
    int c4  = id & 15;
    int row = (id >> 4) & 63;
    int qb  = (id >> 10) & 63;
    int b   = id >> 16;
    int nch = qb / KCHUNK + 1;
    int base_item = (b * NQB + qb) * MAXCH;

    float4 acc = make_float4(0.f, 0.f, 0.f, 0.f);
    float lac = 0.f;
    for (int ci = 0; ci < nch; ci++) {
        const float4 v = *(const float4*)&g_opart[(size_t)(base_item + ci) * 4096 + row * 64 + c4 * 4];
        acc.x += v.x; acc.y += v.y; acc.z += v.z; acc.w += v.w;
        lac += g_lpart[(base_item + ci) * 64 + row];
    }
    float inv = 1.0f / lac;
    acc.x *= inv; acc.y *= inv; acc.z *= inv; acc.w *= inv;
    size_t orow = ((size_t)b * LSEQ + (size_t)qb * 64 + row) * DKH;
    *(float4*)&out[orow + c4 * 4] = acc;
}

// ---------------------------------------------------------------------------
extern "C" void kernel_launch(void* const* d_in, const int* in_sizes, int n_in,
                              void* d_out, int out_size)
{
    const float* Q  = (const float*)d_in[0];
    const float* K  = (const float*)d_in[1];
    const float* V  = (const float*)d_in[2];
    const float* Wq = (const float*)d_in[3];
    const float* bq = (const float*)d_in[4];
    const float* Wk = (const float*)d_in[5];
    const float* bk = (const float*)d_in[6];
    const float* Wv = (const float*)d_in[7];
    const float* bv = (const float*)d_in[8];
    float* out = (float*)d_out;

    cudaFuncSetAttribute(proj6_kernel, cudaFuncAttributeMaxDynamicSharedMemorySize,
                         P6_SMEM_BYTES);
    cudaFuncSetAttribute(attn_part_kernel, cudaFuncAttributeMaxDynamicSharedMemorySize,
                         ATT_SMEM_BYTES);

    wfrag16_kernel<<<96, 256>>>(Wq, Wk, Wv);

    dim3 pg(MROWS / 128, 1, 3);
    proj6_kernel<<<pg, 256, P6_SMEM_BYTES>>>(Q, K, V, bq, bk, bv);

    repack_kernel<<<512, 256>>>();

    dim3 ag(MAXCH, NQB, BATCH);
    attn_part_kernel<<<ag, 256, ATT_SMEM_BYTES>>>();

    attn_reduce_kernel<<<1024, 256>>>(out);
}

// round 13
// speedup vs baseline: 1.1073x; 1.1073x over previous
#include <cuda_runtime.h>
#include <cstdint>

#define BATCH 4
#define LSEQ 4096
#define DMODEL_ 1024
#define DKH 64
#define MROWS (BATCH*LSEQ)   // 16384
#define NQB (LSEQ/64)        // 64 q-blocks per batch
#define KCHUNK 16            // key tiles per split-K work item
#define MAXCH (NQB/KCHUNK)   // 4 chunks max per q-block
#define NTILES (BATCH*NQB)   // 256 key tiles total

// projected q,v as fp16 (half2 packed in uint32), row-major [row][32 half2]
// q pre-scaled by 0.125*log2(e)
__device__ uint32_t g_q[MROWS*32];
__device__ uint32_t g_v[MROWS*32];

// fp16 B-fragment-ordered weights: [slice 3][kt 64][ntp 4][lane 32] uint4
__device__ uint4 g_wf16[3*8192];

// mma-fragment-ordered K/V tiles (fp16): per tile 512 uint4 (8KB)
// g_kf written DIRECTLY by proj (K C-fragments are already attn B-fragments)
__device__ uint4 g_kf[NTILES*512];
__device__ uint4 g_vf[NTILES*512];

// split-K partials (only for qb >= KCHUNK): item = (b*64+qb)*MAXCH + ci
__device__ float g_opart[(size_t)BATCH*NQB*MAXCH*4096];
__device__ float g_lpart[BATCH*NQB*MAXCH*64];

// pack two fp32 -> half2 (lo in low half)
__device__ __forceinline__ uint32_t packh2(float lo, float hi) {
    uint32_t d;
    asm("cvt.rn.f16x2.f32 %0, %1, %2;" : "=r"(d) : "f"(hi), "f"(lo));
    return d;
}

__device__ __forceinline__ float ex2f(float x) {
    float r;
    asm("ex2.approx.f32 %0, %1;" : "=f"(r) : "f"(x));
    return r;
}

__device__ __forceinline__ void mma_f16(float c[4],
    uint32_t a0, uint32_t a1, uint32_t a2, uint32_t a3,
    uint32_t b0, uint32_t b1)
{
    asm volatile(
        "mma.sync.aligned.m16n8k16.row.col.f32.f16.f16.f32 "
        "{%0,%1,%2,%3}, {%4,%5,%6,%7}, {%8,%9}, {%0,%1,%2,%3};\n"
        : "+f"(c[0]), "+f"(c[1]), "+f"(c[2]), "+f"(c[3])
        : "r"(a0), "r"(a1), "r"(a2), "r"(a3), "r"(b0), "r"(b1));
}

__device__ __forceinline__ void cp16(uint32_t saddr, const void* g) {
    asm volatile("cp.async.cg.shared.global [%0], [%1], 16;" :: "r"(saddr), "l"(g));
}
#define CP_COMMIT() asm volatile("cp.async.commit_group;")
#define CP_WAIT0()  asm volatile("cp.async.wait_group 0;")
#define CP_WAIT2()  asm volatile("cp.async.wait_group 2;")

// ---------------------------------------------------------------------------
// Setup: fp16 fragment-ordered W. idx -> (slice, kt 0..63, ntp 0..3, lane).
// ---------------------------------------------------------------------------
__global__ void wfrag16_kernel(const float* __restrict__ Wq,
                               const float* __restrict__ Wk,
                               const float* __restrict__ Wv)
{
    int idx = blockIdx.x * 256 + threadIdx.x;   // 24576 total
    int slice = idx >> 13;
    int rem = idx & 8191;
    int kt = rem >> 7;
    int ntp = (rem >> 5) & 3;
    int l = rem & 31;
    int g = l >> 2, t = l & 3;
    const float* W = (slice == 0) ? Wq : (slice == 1) ? Wk : Wv;
    int n0 = 2 * ntp * 8 + g;
    int k0 = 16 * kt + 2 * t;
    uint4 v;
    v.x = packh2(W[k0 * DKH + n0],           W[(k0 + 1) * DKH + n0]);
    v.y = packh2(W[(k0 + 8) * DKH + n0],     W[(k0 + 9) * DKH + n0]);
    v.z = packh2(W[k0 * DKH + n0 + 8],       W[(k0 + 1) * DKH + n0 + 8]);
    v.w = packh2(W[(k0 + 8) * DKH + n0 + 8], W[(k0 + 9) * DKH + n0 + 8]);
    g_wf16[idx] = v;
}

// ---------------------------------------------------------------------------
// Projection v3 (R8/R11 config, best measured): fp16 m16n8k16.
// 256 threads (8 warps), 128 rows/CTA, k=32 chunks, 4 smem stages,
// 3 chunks in flight.  z=0 -> g_q (scale folds 0.125*log2e);
// z=1 -> g_kf FRAGMENT-DIRECT (C-frag layout == attn K B-frag layout);
// z=2 -> g_v row-major.  grid = (128, 1, 3)
// ---------------------------------------------------------------------------
#define P3_XSTRIDE 36                        // floats per row in a stage
#define P3_XSTAGE_B (128*P3_XSTRIDE*4)       // 18432 B
#define P3_WSTAGE_B 4096                     // 256 uint4
#define P3_SMEM_BYTES (4*P3_XSTAGE_B + 4*P3_WSTAGE_B)   // 90112

__global__ __launch_bounds__(256, 2) void proj3_kernel(
    const float* __restrict__ Qin, const float* __restrict__ Kin, const float* __restrict__ Vin,
    const float* __restrict__ bq, const float* __restrict__ bk, const float* __restrict__ bv)
{
    extern __shared__ char smraw[];
    const float* Xs = (const float*)smraw;                       // [4][128*36]
    const uint4* Ws = (const uint4*)(smraw + 4 * P3_XSTAGE_B);   // [4][256]
    const uint32_t xsb = (uint32_t)__cvta_generic_to_shared(smraw);
    const uint32_t wsb = xsb + 4 * P3_XSTAGE_B;

    const int which = blockIdx.z;
    const float* X    = (which == 0) ? Qin : (which == 1) ? Kin : Vin;
    const float* bias = (which == 0) ? bq  : (which == 1) ? bk  : bv;
    const float scale = (which == 0) ? 0.125f * 1.44269504088896340736f : 1.0f;

    const int tid = threadIdx.x;
    const int w = tid >> 5;
    const int l = tid & 31;
    const int g = l >> 2;
    const int t = l & 3;
    const int row_base = blockIdx.x * 128;
    const float* Xp = X + (size_t)row_base * DMODEL_;
    const uint4* wsrc = g_wf16 + which * 8192;

    float acc[8][4];
    #pragma unroll
    for (int nt = 0; nt < 8; nt++)
        #pragma unroll
        for (int j = 0; j < 4; j++) acc[nt][j] = 0.f;

    auto issue = [&](int ch) {
        if (ch < 32) {
            uint32_t xb = xsb + (uint32_t)(ch & 3) * P3_XSTAGE_B;
            #pragma unroll
            for (int i = 0; i < 4; i++) {
                int f = tid + i * 256;             // 1024 float4 total
                int r = f >> 3, c = f & 7;
                cp16(xb + (uint32_t)(r * P3_XSTRIDE + c * 4) * 4,
                     Xp + (size_t)r * DMODEL_ + ch * 32 + c * 4);
            }
            uint32_t wb = wsb + (uint32_t)(ch & 3) * P3_WSTAGE_B;
            cp16(wb + (uint32_t)tid * 16, wsrc + ch * 256 + tid);
        }
        CP_COMMIT();
    };

    issue(0); issue(1); issue(2);

    const int r0 = 16 * w + g;
    for (int ch = 0; ch < 32; ch++) {
        CP_WAIT2();
        __syncthreads();
        issue(ch + 3);

        const float* Xc = Xs + (ch & 3) * (128 * P3_XSTRIDE);
        const uint4* Wc = Ws + (ch & 3) * 256;

        #pragma unroll
        for (int kk = 0; kk < 2; kk++) {
            int cb = kk * 16 + 2 * t;
            float2 q0 = *(const float2*)&Xc[r0 * P3_XSTRIDE + cb];
            float2 q1 = *(const float2*)&Xc[(r0 + 8) * P3_XSTRIDE + cb];
            float2 q2 = *(const float2*)&Xc[r0 * P3_XSTRIDE + cb + 8];
            float2 q3 = *(const float2*)&Xc[(r0 + 8) * P3_XSTRIDE + cb + 8];
            uint32_t a0 = packh2(q0.x, q0.y);
            uint32_t a1 = packh2(q1.x, q1.y);
            uint32_t a2 = packh2(q2.x, q2.y);
            uint32_t a3 = packh2(q3.x, q3.y);
            #pragma unroll
            for (int ntp = 0; ntp < 4; ntp++) {
                uint4 f = Wc[(kk * 4 + ntp) * 32 + l];
                mma_f16(acc[2 * ntp],     a0, a1, a2, a3, f.x, f.y);
                mma_f16(acc[2 * ntp + 1], a0, a1, a2, a3, f.z, f.w);
            }
        }
    }

    if (which == 1) {
        // K: write attn B-fragments directly (validated in R12).
        // tile T = 2*bx + (w>>2); warp's local key group ntp = w&3.
        const int T = 2 * blockIdx.x + (w >> 2);
        const int ntp = w & 3;
        #pragma unroll
        for (int kt = 0; kt < 4; kt++) {
            int c0 = (2 * kt) * 8 + 2 * t;
            int c1 = (2 * kt + 1) * 8 + 2 * t;
            float b00 = bias[c0], b01 = bias[c0 + 1];
            float b10 = bias[c1], b11 = bias[c1 + 1];
            uint4 v;
            v.x = packh2(acc[2 * kt][0] + b00,     acc[2 * kt][1] + b01);
            v.y = packh2(acc[2 * kt + 1][0] + b10, acc[2 * kt + 1][1] + b11);
            v.z = packh2(acc[2 * kt][2] + b00,     acc[2 * kt][3] + b01);
            v.w = packh2(acc[2 * kt + 1][2] + b10, acc[2 * kt + 1][3] + b11);
            g_kf[T * 512 + (kt * 4 + ntp) * 32 + l] = v;
        }
    } else {
        uint32_t* Y = (which == 0) ? g_q : g_v;
        #pragma unroll
        for (int nt = 0; nt < 8; nt++) {
            int c = nt * 8 + 2 * t;
            float b0v = bias[c], b1v = bias[c + 1];
            Y[(size_t)(row_base + r0) * 32 + nt * 4 + t] =
                packh2((acc[nt][0] + b0v) * scale, (acc[nt][1] + b1v) * scale);
            Y[(size_t)(row_base + r0 + 8) * 32 + nt * 4 + t] =
                packh2((acc[nt][2] + b0v) * scale, (acc[nt][3] + b1v) * scale);
        }
    }
}

// ---------------------------------------------------------------------------
// Repack V only into PV B-fragment order (K fused into proj).
// ---------------------------------------------------------------------------
__global__ void repack_kernel()
{
    int idx = blockIdx.x * 256 + threadIdx.x;   // 131072
    int T = idx >> 9;
    int r = idx & 511;
    int kt = r >> 7;
    int ntp = (r >> 5) & 3;
    int l = r & 31;
    int g = l >> 2, t = l & 3;
    int row0 = T * 64;

    const unsigned short* vh = (const unsigned short*)g_v;

    uint4 vv;
    {
        int kr = row0 + kt * 16;
        int nt = 2 * ntp;
        int col = nt * 8 + g;
        unsigned v0 = vh[(size_t)(kr + 2 * t) * 64 + col];
        unsigned v1 = vh[(size_t)(kr + 2 * t + 1) * 64 + col];
        unsigned v2 = vh[(size_t)(kr + 2 * t + 8) * 64 + col];
        unsigned v3 = vh[(size_t)(kr + 2 * t + 9) * 64 + col];
        vv.x = v0 | (v1 << 16);
        vv.y = v2 | (v3 << 16);
        col += 8;
        v0 = vh[(size_t)(kr + 2 * t) * 64 + col];
        v1 = vh[(size_t)(kr + 2 * t + 1) * 64 + col];
        v2 = vh[(size_t)(kr + 2 * t + 8) * 64 + col];
        v3 = vh[(size_t)(kr + 2 * t + 9) * 64 + col];
        vv.z = v0 | (v1 << 16);
        vv.w = v2 | (v3 << 16);
    }
    g_vf[idx] = vv;
}

// ---------------------------------------------------------------------------
// Attention stage 1 (fp16 m16n8k16): split-K partials, KCHUNK=16.
// Mainloop identical to R11. Epilogue: single-chunk items (qb < KCHUNK)
// normalize and write out DIRECTLY; others write opart/lpart.
// grid = (4 ci, 64 qb, 4 b)
// ---------------------------------------------------------------------------
#define ATT_SMEM_BYTES 32768

__global__ __launch_bounds__(256, 2) void attn_part_kernel(float* __restrict__ out)
{
    extern __shared__ uint4 sm4[];
    const uint32_t smb = (uint32_t)__cvta_generic_to_shared(sm4);

    const int ci = blockIdx.x;
    const int qb = blockIdx.y;
    const int b  = blockIdx.z;
    const int kstart = ci * KCHUNK;
    if (kstart > qb) return;
    const int kend = min(kstart + KCHUNK, qb + 1);

    const int tid = threadIdx.x;
    const int w = tid >> 5;
    const int l = tid & 31;
    const int g = l >> 2;
    const int t = l & 3;
    const int wr = w & 3;
    const int wg = w >> 2;

    uint32_t qa[4][4];
    {
        const uint32_t* qu = g_q + ((size_t)b * LSEQ + (size_t)qb * 64 + 16 * wr + g) * 32;
        const uint32_t* qu8 = qu + 8 * 32;
        #pragma unroll
        for (int kt = 0; kt < 4; kt++) {
            qa[kt][0] = qu[kt * 8 + t];
            qa[kt][1] = qu8[kt * 8 + t];
            qa[kt][2] = qu[kt * 8 + t + 4];
            qa[kt][3] = qu8[kt * 8 + t + 4];
        }
    }

    float o[8][4];
    #pragma unroll
    for (int nt = 0; nt < 8; nt++)
        #pragma unroll
        for (int j = 0; j < 4; j++) o[nt][j] = 0.f;
    float lfrag[4] = {0.f, 0.f, 0.f, 0.f};
    const uint32_t ONES = 0x3C003C00u;

    auto stage = [&](int kb, int p) {
        const uint4* kp = g_kf + (size_t)(b * NQB + kb) * 512;
        const uint4* vp = g_vf + (size_t)(b * NQB + kb) * 512;
        uint32_t kd = smb + (uint32_t)p * 8192;
        uint32_t vd = smb + 16384u + (uint32_t)p * 8192;
        #pragma unroll
        for (int i = 0; i < 2; i++) {
            int u = tid + i * 256;
            cp16(kd + (uint32_t)u * 16, kp + u);
            cp16(vd + (uint32_t)u * 16, vp + u);
        }
        CP_COMMIT();
    };

    stage(kstart, 0);

    for (int kb = kstart; kb < kend; kb++) {
        const int p = (kb - kstart) & 1;
        CP_WAIT0();
        __syncthreads();
        const uint4* Kc = sm4 + p * 512;
        const uint4* Vc = sm4 + 1024 + p * 512;

        if (kb + 1 < kend) stage(kb + 1, 1 - p);

        float s[4][4];
        #pragma unroll
        for (int ntl = 0; ntl < 4; ntl++)
            #pragma unroll
            for (int j = 0; j < 4; j++) s[ntl][j] = 0.f;

        #pragma unroll
        for (int kt = 0; kt < 4; kt++) {
            #pragma unroll
            for (int pp = 0; pp < 2; pp++) {
                uint4 f = Kc[(kt * 4 + wg * 2 + pp) * 32 + l];
                mma_f16(s[2 * pp],     qa[kt][0], qa[kt][1], qa[kt][2], qa[kt][3], f.x, f.y);
                mma_f16(s[2 * pp + 1], qa[kt][0], qa[kt][1], qa[kt][2], qa[kt][3], f.z, f.w);
            }
        }

        if (kb == qb) {
            int r0 = 16 * wr + g;
            #pragma unroll
            for (int ntl = 0; ntl < 4; ntl++) {
                int c = (wg * 4 + ntl) * 8 + 2 * t;
                if (c     > r0)     s[ntl][0] = -1e30f;
                if (c + 1 > r0)     s[ntl][1] = -1e30f;
                if (c     > r0 + 8) s[ntl][2] = -1e30f;
                if (c + 1 > r0 + 8) s[ntl][3] = -1e30f;
            }
        }

        #pragma unroll
        for (int ntl = 0; ntl < 4; ntl++) {
            s[ntl][0] = ex2f(s[ntl][0]);
            s[ntl][1] = ex2f(s[ntl][1]);
            s[ntl][2] = ex2f(s[ntl][2]);
            s[ntl][3] = ex2f(s[ntl][3]);
        }

        #pragma unroll
        for (int kk = 0; kk < 2; kk++) {
            uint32_t a0 = packh2(s[2 * kk][0],     s[2 * kk][1]);
            uint32_t a1 = packh2(s[2 * kk][2],     s[2 * kk][3]);
            uint32_t a2 = packh2(s[2 * kk + 1][0], s[2 * kk + 1][1]);
            uint32_t a3 = packh2(s[2 * kk + 1][2], s[2 * kk + 1][3]);
            mma_f16(lfrag, a0, a1, a2, a3, ONES, ONES);
            int kc = wg * 2 + kk;
            #pragma unroll
            for (int ntp = 0; ntp < 4; ntp++) {
                uint4 f = Vc[(kc * 4 + ntp) * 32 + l];
                mma_f16(o[2 * ntp],     a0, a1, a2, a3, f.x, f.y);
                mma_f16(o[2 * ntp + 1], a0, a1, a2, a3, f.z, f.w);
            }
        }
    }

    const float lsum0 = lfrag[0];
    const float lsum1 = lfrag[2];

    float* smemO = (float*)sm4;
    float* lvec  = (float*)sm4 + 64 * 68;

    __syncthreads();
    if (wg == 0) {
        #pragma unroll
        for (int nt = 0; nt < 8; nt++) {
            int c = nt * 8 + 2 * t;
            smemO[(16 * wr + g) * 68 + c]         = o[nt][0];
            smemO[(16 * wr + g) * 68 + c + 1]     = o[nt][1];
            smemO[(16 * wr + g + 8) * 68 + c]     = o[nt][2];
            smemO[(16 * wr + g + 8) * 68 + c + 1] = o[nt][3];
        }
        if (t == 0) { lvec[16 * wr + g] = lsum0; lvec[16 * wr + g + 8] = lsum1; }
    }
    __syncthreads();
    if (wg == 1) {
        #pragma unroll
        for (int nt = 0; nt < 8; nt++) {
            int c = nt * 8 + 2 * t;
            smemO[(16 * wr + g) * 68 + c]         += o[nt][0];
            smemO[(16 * wr + g) * 68 + c + 1]     += o[nt][1];
            smemO[(16 * wr + g + 8) * 68 + c]     += o[nt][2];
            smemO[(16 * wr + g + 8) * 68 + c + 1] += o[nt][3];
        }
        if (t == 0) { lvec[16 * wr + g] += lsum0; lvec[16 * wr + g + 8] += lsum1; }
    }
    __syncthreads();

    {
        int row = tid >> 2;
        int c0 = (tid & 3) * 16;
        if (qb < KCHUNK) {
            // single-chunk q-block: finalize directly, skip opart/reduce
            float inv = 1.0f / lvec[row];
            size_t orow = ((size_t)b * LSEQ + (size_t)qb * 64 + row) * DKH;
            #pragma unroll
            for (int j = 0; j < 4; j++) {
                float4 v = *(float4*)&smemO[row * 68 + c0 + j * 4];
                v.x *= inv; v.y *= inv; v.z *= inv; v.w *= inv;
                *(float4*)&out[orow + c0 + j * 4] = v;
            }
        } else {
            const int item = (b * NQB + qb) * MAXCH + ci;
            float* dst = g_opart + (size_t)item * 4096;
            #pragma unroll
            for (int j = 0; j < 4; j++)
                *(float4*)&dst[row * 64 + c0 + j * 4] = *(float4*)&smemO[row * 68 + c0 + j * 4];
            if ((tid & 3) == 0) g_lpart[item * 64 + row] = lvec[row];
        }
    }
}

// ---------------------------------------------------------------------------
// Attention stage 2: elementwise reduce, qb >= KCHUNK only.
// 196608 threads: id -> (b, qb-16 of 48, row, c4)
// ---------------------------------------------------------------------------
__global__ __launch_bounds__(256) void attn_reduce_kernel(float* __restrict__ out)
{
    int id = blockIdx.x * 256 + threadIdx.x;   // 196608
    int c4  = id & 15;
    int row = (id >> 4) & 63;
    int rem = id >> 10;                        // 0..191 = b*48 + (qb-16)
    int b   = rem / 48;
    int qb  = 16 + rem % 48;
    int nch = qb / KCHUNK + 1;                 // 2..4
    int base_item = (b * NQB + qb) * MAXCH;

    float4 acc = make_float4(0.f, 0.f, 0.f, 0.f);
    float lac = 0.f;
    for (int ci = 0; ci < nch; ci++) {
        const float4 v = *(const float4*)&g_opart[(size_t)(base_item + ci) * 4096 + row * 64 + c4 * 4];
        acc.x += v.x; acc.y += v.y; acc.z += v.z; acc.w += v.w;
        lac += g_lpart[(base_item + ci) * 64 + row];
    }
    float inv = 1.0f / lac;
    acc.x *= inv; acc.y *= inv; acc.z *= inv; acc.w *= inv;
    size_t orow = ((size_t)b * LSEQ + (size_t)qb * 64 + row) * DKH;
    *(float4*)&out[orow + c4 * 4] = acc;
}

// ---------------------------------------------------------------------------
extern "C" void kernel_launch(void* const* d_in, const int* in_sizes, int n_in,
                              void* d_out, int out_size)
{
    const float* Q  = (const float*)d_in[0];
    const float* K  = (const float*)d_in[1];
    const float* V  = (const float*)d_in[2];
    const float* Wq = (const float*)d_in[3];
    const float* bq = (const float*)d_in[4];
    const float* Wk = (const float*)d_in[5];
    const float* bk = (const float*)d_in[6];
    const float* Wv = (const float*)d_in[7];
    const float* bv = (const float*)d_in[8];
    float* out = (float*)d_out;

    cudaFuncSetAttribute(proj3_kernel, cudaFuncAttributeMaxDynamicSharedMemorySize,
                         P3_SMEM_BYTES);
    cudaFuncSetAttribute(attn_part_kernel, cudaFuncAttributeMaxDynamicSharedMemorySize,
                         ATT_SMEM_BYTES);

    wfrag16_kernel<<<96, 256>>>(Wq, Wk, Wv);

    dim3 pg(MROWS / 128, 1, 3);
    proj3_kernel<<<pg, 256, P3_SMEM_BYTES>>>(Q, K, V, bq, bk, bv);

    repack_kernel<<<512, 256>>>();

    dim3 ag(MAXCH, NQB, BATCH);
    attn_part_kernel<<<ag, 256, ATT_SMEM_BYTES>>>(out);

    attn_reduce_kernel<<<768, 256>>>(out);
}

// round 14
// speedup vs baseline: 1.1558x; 1.0438x over previous
#include <cuda_runtime.h>
#include <cstdint>

#define BATCH 4
#define LSEQ 4096
#define DMODEL_ 1024
#define DKH 64
#define MROWS (BATCH*LSEQ)   // 16384
#define NQB 64               // 64-key tiles per batch
#define NQB2 32              // 128-row q-blocks per batch
#define KCHUNK 8             // key tiles per split-K work item
#define MAXCH 8              // max chunks per 128-row q-block
#define NTILES (BATCH*NQB)   // 256 key tiles total

// projected q,v as fp16 (half2 packed in uint32), row-major [row][32 half2]
// q pre-scaled by 0.125*log2(e)
__device__ uint32_t g_q[MROWS*32];
__device__ uint32_t g_v[MROWS*32];

// fp16 B-fragment-ordered weights: [slice 3][kt 64][ntp 4][lane 32] uint4
__device__ uint4 g_wf16[3*8192];

// mma-fragment-ordered K/V tiles (fp16): per tile 512 uint4 (8KB)
// g_kf written DIRECTLY by proj (K C-fragments are already attn B-fragments)
__device__ uint4 g_kf[NTILES*512];
__device__ uint4 g_vf[NTILES*512];

// split-K partials (only for Q >= 4): item = (b*32+Q)*MAXCH + ci
// each item: 128 rows x 64 cols O + 128 l values
__device__ float g_opart[(size_t)BATCH*NQB2*MAXCH*8192];   // 33.5 MB
__device__ float g_lpart[BATCH*NQB2*MAXCH*128];

// pack two fp32 -> half2 (lo in low half)
__device__ __forceinline__ uint32_t packh2(float lo, float hi) {
    uint32_t d;
    asm("cvt.rn.f16x2.f32 %0, %1, %2;" : "=r"(d) : "f"(hi), "f"(lo));
    return d;
}

__device__ __forceinline__ float ex2f(float x) {
    float r;
    asm("ex2.approx.f32 %0, %1;" : "=f"(r) : "f"(x));
    return r;
}

__device__ __forceinline__ void mma_f16(float c[4],
    uint32_t a0, uint32_t a1, uint32_t a2, uint32_t a3,
    uint32_t b0, uint32_t b1)
{
    asm volatile(
        "mma.sync.aligned.m16n8k16.row.col.f32.f16.f16.f32 "
        "{%0,%1,%2,%3}, {%4,%5,%6,%7}, {%8,%9}, {%0,%1,%2,%3};\n"
        : "+f"(c[0]), "+f"(c[1]), "+f"(c[2]), "+f"(c[3])
        : "r"(a0), "r"(a1), "r"(a2), "r"(a3), "r"(b0), "r"(b1));
}

__device__ __forceinline__ void cp16(uint32_t saddr, const void* g) {
    asm volatile("cp.async.cg.shared.global [%0], [%1], 16;" :: "r"(saddr), "l"(g));
}
#define CP_COMMIT() asm volatile("cp.async.commit_group;")
#define CP_WAIT0()  asm volatile("cp.async.wait_group 0;")
#define CP_WAIT2()  asm volatile("cp.async.wait_group 2;")

// ---------------------------------------------------------------------------
// Setup: fp16 fragment-ordered W. idx -> (slice, kt 0..63, ntp 0..3, lane).
// ---------------------------------------------------------------------------
__global__ void wfrag16_kernel(const float* __restrict__ Wq,
                               const float* __restrict__ Wk,
                               const float* __restrict__ Wv)
{
    int idx = blockIdx.x * 256 + threadIdx.x;   // 24576 total
    int slice = idx >> 13;
    int rem = idx & 8191;
    int kt = rem >> 7;
    int ntp = (rem >> 5) & 3;
    int l = rem & 31;
    int g = l >> 2, t = l & 3;
    const float* W = (slice == 0) ? Wq : (slice == 1) ? Wk : Wv;
    int n0 = 2 * ntp * 8 + g;
    int k0 = 16 * kt + 2 * t;
    uint4 v;
    v.x = packh2(W[k0 * DKH + n0],           W[(k0 + 1) * DKH + n0]);
    v.y = packh2(W[(k0 + 8) * DKH + n0],     W[(k0 + 9) * DKH + n0]);
    v.z = packh2(W[k0 * DKH + n0 + 8],       W[(k0 + 1) * DKH + n0 + 8]);
    v.w = packh2(W[(k0 + 8) * DKH + n0 + 8], W[(k0 + 9) * DKH + n0 + 8]);
    g_wf16[idx] = v;
}

// ---------------------------------------------------------------------------
// Projection v3 (best measured, unchanged from R13): fp16 m16n8k16.
// z=0 -> g_q (scale folds 0.125*log2e); z=1 -> g_kf FRAGMENT-DIRECT;
// z=2 -> g_v row-major.  grid = (128, 1, 3)
// ---------------------------------------------------------------------------
#define P3_XSTRIDE 36
#define P3_XSTAGE_B (128*P3_XSTRIDE*4)
#define P3_WSTAGE_B 4096
#define P3_SMEM_BYTES (4*P3_XSTAGE_B + 4*P3_WSTAGE_B)   // 90112

__global__ __launch_bounds__(256, 2) void proj3_kernel(
    const float* __restrict__ Qin, const float* __restrict__ Kin, const float* __restrict__ Vin,
    const float* __restrict__ bq, const float* __restrict__ bk, const float* __restrict__ bv)
{
    extern __shared__ char smraw[];
    const float* Xs = (const float*)smraw;
    const uint4* Ws = (const uint4*)(smraw + 4 * P3_XSTAGE_B);
    const uint32_t xsb = (uint32_t)__cvta_generic_to_shared(smraw);
    const uint32_t wsb = xsb + 4 * P3_XSTAGE_B;

    const int which = blockIdx.z;
    const float* X    = (which == 0) ? Qin : (which == 1) ? Kin : Vin;
    const float* bias = (which == 0) ? bq  : (which == 1) ? bk  : bv;
    const float scale = (which == 0) ? 0.125f * 1.44269504088896340736f : 1.0f;

    const int tid = threadIdx.x;
    const int w = tid >> 5;
    const int l = tid & 31;
    const int g = l >> 2;
    const int t = l & 3;
    const int row_base = blockIdx.x * 128;
    const float* Xp = X + (size_t)row_base * DMODEL_;
    const uint4* wsrc = g_wf16 + which * 8192;

    float acc[8][4];
    #pragma unroll
    for (int nt = 0; nt < 8; nt++)
        #pragma unroll
        for (int j = 0; j < 4; j++) acc[nt][j] = 0.f;

    auto issue = [&](int ch) {
        if (ch < 32) {
            uint32_t xb = xsb + (uint32_t)(ch & 3) * P3_XSTAGE_B;
            #pragma unroll
            for (int i = 0; i < 4; i++) {
                int f = tid + i * 256;
                int r = f >> 3, c = f & 7;
                cp16(xb + (uint32_t)(r * P3_XSTRIDE + c * 4) * 4,
                     Xp + (size_t)r * DMODEL_ + ch * 32 + c * 4);
            }
            uint32_t wb = wsb + (uint32_t)(ch & 3) * P3_WSTAGE_B;
            cp16(wb + (uint32_t)tid * 16, wsrc + ch * 256 + tid);
        }
        CP_COMMIT();
    };

    issue(0); issue(1); issue(2);

    const int r0 = 16 * w + g;
    for (int ch = 0; ch < 32; ch++) {
        CP_WAIT2();
        __syncthreads();
        issue(ch + 3);

        const float* Xc = Xs + (ch & 3) * (128 * P3_XSTRIDE);
        const uint4* Wc = Ws + (ch & 3) * 256;

        #pragma unroll
        for (int kk = 0; kk < 2; kk++) {
            int cb = kk * 16 + 2 * t;
            float2 q0 = *(const float2*)&Xc[r0 * P3_XSTRIDE + cb];
            float2 q1 = *(const float2*)&Xc[(r0 + 8) * P3_XSTRIDE + cb];
            float2 q2 = *(const float2*)&Xc[r0 * P3_XSTRIDE + cb + 8];
            float2 q3 = *(const float2*)&Xc[(r0 + 8) * P3_XSTRIDE + cb + 8];
            uint32_t a0 = packh2(q0.x, q0.y);
            uint32_t a1 = packh2(q1.x, q1.y);
            uint32_t a2 = packh2(q2.x, q2.y);
            uint32_t a3 = packh2(q3.x, q3.y);
            #pragma unroll
            for (int ntp = 0; ntp < 4; ntp++) {
                uint4 f = Wc[(kk * 4 + ntp) * 32 + l];
                mma_f16(acc[2 * ntp],     a0, a1, a2, a3, f.x, f.y);
                mma_f16(acc[2 * ntp + 1], a0, a1, a2, a3, f.z, f.w);
            }
        }
    }

    if (which == 1) {
        const int T = 2 * blockIdx.x + (w >> 2);
        const int ntp = w & 3;
        #pragma unroll
        for (int kt = 0; kt < 4; kt++) {
            int c0 = (2 * kt) * 8 + 2 * t;
            int c1 = (2 * kt + 1) * 8 + 2 * t;
            float b00 = bias[c0], b01 = bias[c0 + 1];
            float b10 = bias[c1], b11 = bias[c1 + 1];
            uint4 v;
            v.x = packh2(acc[2 * kt][0] + b00,     acc[2 * kt][1] + b01);
            v.y = packh2(acc[2 * kt + 1][0] + b10, acc[2 * kt + 1][1] + b11);
            v.z = packh2(acc[2 * kt][2] + b00,     acc[2 * kt][3] + b01);
            v.w = packh2(acc[2 * kt + 1][2] + b10, acc[2 * kt + 1][3] + b11);
            g_kf[T * 512 + (kt * 4 + ntp) * 32 + l] = v;
        }
    } else {
        uint32_t* Y = (which == 0) ? g_q : g_v;
        #pragma unroll
        for (int nt = 0; nt < 8; nt++) {
            int c = nt * 8 + 2 * t;
            float b0v = bias[c], b1v = bias[c + 1];
            Y[(size_t)(row_base + r0) * 32 + nt * 4 + t] =
                packh2((acc[nt][0] + b0v) * scale, (acc[nt][1] + b1v) * scale);
            Y[(size_t)(row_base + r0 + 8) * 32 + nt * 4 + t] =
                packh2((acc[nt][2] + b0v) * scale, (acc[nt][3] + b1v) * scale);
        }
    }
}

// ---------------------------------------------------------------------------
// Repack V only into PV B-fragment order (unchanged).
// ---------------------------------------------------------------------------
__global__ void repack_kernel()
{
    int idx = blockIdx.x * 256 + threadIdx.x;   // 131072
    int T = idx >> 9;
    int r = idx & 511;
    int kt = r >> 7;
    int ntp = (r >> 5) & 3;
    int l = r & 31;
    int g = l >> 2, t = l & 3;
    int row0 = T * 64;

    const unsigned short* vh = (const unsigned short*)g_v;

    uint4 vv;
    {
        int kr = row0 + kt * 16;
        int nt = 2 * ntp;
        int col = nt * 8 + g;
        unsigned v0 = vh[(size_t)(kr + 2 * t) * 64 + col];
        unsigned v1 = vh[(size_t)(kr + 2 * t + 1) * 64 + col];
        unsigned v2 = vh[(size_t)(kr + 2 * t + 8) * 64 + col];
        unsigned v3 = vh[(size_t)(kr + 2 * t + 9) * 64 + col];
        vv.x = v0 | (v1 << 16);
        vv.y = v2 | (v3 << 16);
        col += 8;
        v0 = vh[(size_t)(kr + 2 * t) * 64 + col];
        v1 = vh[(size_t)(kr + 2 * t + 1) * 64 + col];
        v2 = vh[(size_t)(kr + 2 * t + 8) * 64 + col];
        v3 = vh[(size_t)(kr + 2 * t + 9) * 64 + col];
        vv.z = v0 | (v1 << 16);
        vv.w = v2 | (v3 << 16);
    }
    g_vf[idx] = vv;
}

// ---------------------------------------------------------------------------
// Attention stage 1: 128-row q-blocks, warp = 16 rows x 64 keys (no key
// split). Per warp per tile: 8 K LDS.128 + 32 S-mma + 32 ex2 + 16 packs +
// 4 lsum-mma + 16 V LDS.128 + 32 PV-mma. No cross-warp combine; epilogue
// writes O straight from registers. grid = (8 ci, 32 Q, 4 b)
// ---------------------------------------------------------------------------
#define ATT_SMEM_BYTES 32768

__global__ __launch_bounds__(256, 2) void attn_part_kernel(float* __restrict__ out)
{
    extern __shared__ uint4 sm4[];
    const uint32_t smb = (uint32_t)__cvta_generic_to_shared(sm4);

    const int ci = blockIdx.x;
    const int Q  = blockIdx.y;          // 128-row q-block
    const int b  = blockIdx.z;
    const int ntiles = 2 * Q + 2;
    const int kstart = ci * KCHUNK;
    if (kstart >= ntiles) return;
    const int kend = min(kstart + KCHUNK, ntiles);

    const int tid = threadIdx.x;
    const int w = tid >> 5;             // row group: rows 16w..16w+15
    const int l = tid & 31;
    const int g = l >> 2;
    const int t = l & 3;

    // Q A-frags for rows 128Q+16w+g, +8
    uint32_t qa[4][4];
    {
        const uint32_t* qu = g_q + ((size_t)b * LSEQ + (size_t)Q * 128 + 16 * w + g) * 32;
        const uint32_t* qu8 = qu + 8 * 32;
        #pragma unroll
        for (int kt = 0; kt < 4; kt++) {
            qa[kt][0] = qu[kt * 8 + t];
            qa[kt][1] = qu8[kt * 8 + t];
            qa[kt][2] = qu[kt * 8 + t + 4];
            qa[kt][3] = qu8[kt * 8 + t + 4];
        }
    }

    float o[8][4];
    #pragma unroll
    for (int nt = 0; nt < 8; nt++)
        #pragma unroll
        for (int j = 0; j < 4; j++) o[nt][j] = 0.f;
    float lfrag[4] = {0.f, 0.f, 0.f, 0.f};
    const uint32_t ONES = 0x3C003C00u;

    auto stage = [&](int kb, int p) {
        const uint4* kp = g_kf + (size_t)(b * NQB + kb) * 512;
        const uint4* vp = g_vf + (size_t)(b * NQB + kb) * 512;
        uint32_t kd = smb + (uint32_t)p * 8192;
        uint32_t vd = smb + 16384u + (uint32_t)p * 8192;
        #pragma unroll
        for (int i = 0; i < 2; i++) {
            int u = tid + i * 256;
            cp16(kd + (uint32_t)u * 16, kp + u);
            cp16(vd + (uint32_t)u * 16, vp + u);
        }
        CP_COMMIT();
    };

    stage(kstart, 0);

    for (int kb = kstart; kb < kend; kb++) {
        const int p = (kb - kstart) & 1;
        CP_WAIT0();
        __syncthreads();
        const uint4* Kc = sm4 + p * 512;
        const uint4* Vc = sm4 + 1024 + p * 512;

        if (kb + 1 < kend) stage(kb + 1, 1 - p);

        // ---- S' = Q @ K^T over all 64 keys ----
        float s[8][4];
        #pragma unroll
        for (int nt = 0; nt < 8; nt++)
            #pragma unroll
            for (int j = 0; j < 4; j++) s[nt][j] = 0.f;

        #pragma unroll
        for (int kt = 0; kt < 4; kt++) {
            #pragma unroll
            for (int pp = 0; pp < 4; pp++) {
                uint4 f = Kc[(kt * 4 + pp) * 32 + l];
                mma_f16(s[2 * pp],     qa[kt][0], qa[kt][1], qa[kt][2], qa[kt][3], f.x, f.y);
                mma_f16(s[2 * pp + 1], qa[kt][0], qa[kt][1], qa[kt][2], qa[kt][3], f.z, f.w);
            }
        }

        // causal mask: key 64kb+c vs row 128Q+16w+g(+8)
        {
            const int d = 64 * kb - 128 * Q;
            if (d + 63 > 16 * w) {
                int thr0 = 16 * w + g - d;       // mask col c if c > thr0 (row g)
                #pragma unroll
                for (int nt = 0; nt < 8; nt++) {
                    int c = nt * 8 + 2 * t;
                    if (c     > thr0)     s[nt][0] = -1e30f;
                    if (c + 1 > thr0)     s[nt][1] = -1e30f;
                    if (c     > thr0 + 8) s[nt][2] = -1e30f;
                    if (c + 1 > thr0 + 8) s[nt][3] = -1e30f;
                }
            }
        }

        // ---- P = 2^(S') ----
        #pragma unroll
        for (int nt = 0; nt < 8; nt++) {
            s[nt][0] = ex2f(s[nt][0]);
            s[nt][1] = ex2f(s[nt][1]);
            s[nt][2] = ex2f(s[nt][2]);
            s[nt][3] = ex2f(s[nt][3]);
        }

        // ---- O += P @ V ; lsum += P @ ones ----
        #pragma unroll
        for (int kk = 0; kk < 4; kk++) {
            uint32_t a0 = packh2(s[2 * kk][0],     s[2 * kk][1]);
            uint32_t a1 = packh2(s[2 * kk][2],     s[2 * kk][3]);
            uint32_t a2 = packh2(s[2 * kk + 1][0], s[2 * kk + 1][1]);
            uint32_t a3 = packh2(s[2 * kk + 1][2], s[2 * kk + 1][3]);
            mma_f16(lfrag, a0, a1, a2, a3, ONES, ONES);
            #pragma unroll
            for (int ntp = 0; ntp < 4; ntp++) {
                uint4 f = Vc[(kk * 4 + ntp) * 32 + l];
                mma_f16(o[2 * ntp],     a0, a1, a2, a3, f.x, f.y);
                mma_f16(o[2 * ntp + 1], a0, a1, a2, a3, f.z, f.w);
            }
        }
    }

    // ---- epilogue: direct from registers (no smem, no combine) ----
    const float lsum0 = lfrag[0];   // row 16w+g  (all t lanes identical)
    const float lsum1 = lfrag[2];   // row 16w+g+8

    if (ntiles <= KCHUNK) {
        // whole causal range in one item: normalize and write output
        float inv0 = 1.0f / lsum0, inv1 = 1.0f / lsum1;
        size_t r0 = ((size_t)b * LSEQ + (size_t)Q * 128 + 16 * w + g) * DKH;
        size_t r1 = r0 + 8 * DKH;
        #pragma unroll
        for (int nt = 0; nt < 8; nt++) {
            int c = nt * 8 + 2 * t;
            *(float2*)&out[r0 + c] = make_float2(o[nt][0] * inv0, o[nt][1] * inv0);
            *(float2*)&out[r1 + c] = make_float2(o[nt][2] * inv1, o[nt][3] * inv1);
        }
    } else {
        const int item = (b * NQB2 + Q) * MAXCH + ci;
        float* dst = g_opart + (size_t)item * 8192;
        const int lr = 16 * w + g;
        #pragma unroll
        for (int nt = 0; nt < 8; nt++) {
            int c = nt * 8 + 2 * t;
            *(float2*)&dst[lr * 64 + c]       = make_float2(o[nt][0], o[nt][1]);
            *(float2*)&dst[(lr + 8) * 64 + c] = make_float2(o[nt][2], o[nt][3]);
        }
        if (t == 0) {
            g_lpart[item * 128 + lr]     = lsum0;
            g_lpart[item * 128 + lr + 8] = lsum1;
        }
    }
}

// ---------------------------------------------------------------------------
// Attention stage 2: elementwise reduce, Q >= 4 only.
// 229376 threads: id -> (b, Q-4 of 28, row 0..127, c4)
// ---------------------------------------------------------------------------
__global__ __launch_bounds__(256) void attn_reduce_kernel(float* __restrict__ out)
{
    int id = blockIdx.x * 256 + threadIdx.x;   // 229376
    int c4  = id & 15;
    int row = (id >> 4) & 127;
    int rem = id >> 11;                        // 0..111 = b*28 + (Q-4)
    int b   = rem / 28;
    int Q   = 4 + rem % 28;
    int nch = (2 * Q + 2 + KCHUNK - 1) / KCHUNK;   // 2..8
    int base_item = (b * NQB2 + Q) * MAXCH;

    float4 acc = make_float4(0.f, 0.f, 0.f, 0.f);
    float lac = 0.f;
    for (int ci = 0; ci < nch; ci++) {
        const float4 v = *(const float4*)&g_opart[(size_t)(base_item + ci) * 8192 + row * 64 + c4 * 4];
        acc.x += v.x; acc.y += v.y; acc.z += v.z; acc.w += v.w;
        lac += g_lpart[(base_item + ci) * 128 + row];
    }
    float inv = 1.0f / lac;
    acc.x *= inv; acc.y *= inv; acc.z *= inv; acc.w *= inv;
    size_t orow = ((size_t)b * LSEQ + (size_t)Q * 128 + row) * DKH;
    *(float4*)&out[orow + c4 * 4] = acc;
}

// ---------------------------------------------------------------------------
extern "C" void kernel_launch(void* const* d_in, const int* in_sizes, int n_in,
                              void* d_out, int out_size)
{
    const float* Q  = (const float*)d_in[0];
    const float* K  = (const float*)d_in[1];
    const float* V  = (const float*)d_in[2];
    const float* Wq = (const float*)d_in[3];
    const float* bq = (const float*)d_in[4];
    const float* Wk = (const float*)d_in[5];
    const float* bk = (const float*)d_in[6];
    const float* Wv = (const float*)d_in[7];
    const float* bv = (const float*)d_in[8];
    float* out = (float*)d_out;

    cudaFuncSetAttribute(proj3_kernel, cudaFuncAttributeMaxDynamicSharedMemorySize,
                         P3_SMEM_BYTES);
    cudaFuncSetAttribute(attn_part_kernel, cudaFuncAttributeMaxDynamicSharedMemorySize,
                         ATT_SMEM_BYTES);

    wfrag16_kernel<<<96, 256>>>(Wq, Wk, Wv);

    dim3 pg(MROWS / 128, 1, 3);
    proj3_kernel<<<pg, 256, P3_SMEM_BYTES>>>(Q, K, V, bq, bk, bv);

    repack_kernel<<<512, 256>>>();

    dim3 ag(MAXCH, NQB2, BATCH);
    attn_part_kernel<<<ag, 256, ATT_SMEM_BYTES>>>(out);

    attn_reduce_kernel<<<896, 256>>>(out);
}